// round 5
// baseline (speedup 1.0000x reference)
#include <cuda_runtime.h>

// DRNN: two stacked SimpleRNN(tanh), persistent per-CTA kernel, round 2.
// B=512 rows, T=512 steps, D=64, H=100.
// 128 CTAs x 4 rows; 640 threads = 20 warps:
//   warps 0-9  = layer1 (step i),  warps 10-19 = layer2 (step i-1, pipelined).
// Each warp owns 10 units; each unit's k-reduction is split across 3 lanes
// (lane thirds t=0,1,2 at m, m+10, m+20), combined via two shfl_down.
// Weight thirds live in registers (<=36 u64/thread), quad-interleaved
// (quad q == t mod 3) so every activation LDS.128 is 16B-aligned and
// conflict-free. fma.rn.f32x2 packs 2 MACs/instr.

#define TT   512
#define BB   512
#define DD   64
#define HH   100
#define ROWS 4
#define XS   72    // padded x row stride (18 quads; covers padded iter q<=17)
#define HS   108   // padded h row stride (27 quads; covers padded iter q<=26)
#define NXI  6     // ceil(16 x-quads / 3)
#define NHI  9     // ceil(25 h-quads / 3)
#define NTHR 640

__device__ __forceinline__ void ffma2(unsigned long long &acc,
                                      unsigned long long a,
                                      unsigned long long b) {
    asm("fma.rn.f32x2 %0, %1, %2, %0;" : "+l"(acc) : "l"(a), "l"(b));
}

__device__ __forceinline__ unsigned long long pack2(float lo, float hi) {
    unsigned long long r;
    asm("mov.b64 %0, {%1, %2};" : "=l"(r) : "f"(lo), "f"(hi));
    return r;
}

__device__ __forceinline__ float hsum2(unsigned long long v) {
    float lo, hi;
    asm("mov.b64 {%0, %1}, %2;" : "=f"(lo), "=f"(hi) : "l"(v));
    return lo + hi;
}

__device__ __forceinline__ ulonglong2 lds128(const float* p) {
    return *reinterpret_cast<const ulonglong2*>(p);
}

// Accurate tanh via exp (immune to fast-math tanhf substitution).
__device__ __forceinline__ float tanh_f(float x) {
    float ax = fabsf(x);
    float e  = __expf(-2.0f * ax);
    float r  = (1.0f - e) / (1.0f + e);
    return copysignf(r, x);
}

// Accumulate NQ quad-iterations over 4 rows from base pointer (already offset
// by 4*tt floats). Row stride RS floats, weights at w[WOFF + 2*it (+1)].
template<int NQ, int WOFF, int RS>
__device__ __forceinline__ void accum4(unsigned long long &a0, unsigned long long &a1,
                                       unsigned long long &a2, unsigned long long &a3,
                                       const float* base,
                                       const unsigned long long (&w)[36])
{
    #pragma unroll
    for (int it = 0; it < NQ; ++it) {
        ulonglong2 v0 = lds128(base + 0*RS + 12*it);
        ulonglong2 v1 = lds128(base + 1*RS + 12*it);
        ulonglong2 v2 = lds128(base + 2*RS + 12*it);
        ulonglong2 v3 = lds128(base + 3*RS + 12*it);
        unsigned long long wA = w[WOFF + 2*it];
        unsigned long long wB = w[WOFF + 2*it + 1];
        ffma2(a0, v0.x, wA); ffma2(a1, v1.x, wA);
        ffma2(a2, v2.x, wA); ffma2(a3, v3.x, wA);
        ffma2(a0, v0.y, wB); ffma2(a1, v1.y, wB);
        ffma2(a2, v2.y, wB); ffma2(a3, v3.y, wB);
    }
}

__device__ __forceinline__ float combine3(float p) {
    float a = __shfl_down_sync(0xffffffffu, p, 10);
    float b = __shfl_down_sync(0xffffffffu, p, 20);
    return p + a + b;          // valid for lanes 0-9
}

__global__ __launch_bounds__(NTHR, 1)
void drnn_kernel(const float* __restrict__ X,
                 const float* __restrict__ W1x, const float* __restrict__ W1h,
                 const float* __restrict__ B1,
                 const float* __restrict__ W2x, const float* __restrict__ W2h,
                 const float* __restrict__ B2,
                 const float* __restrict__ Wo,  const float* __restrict__ Bo,
                 float* __restrict__ out)
{
    __shared__ __align__(16) float sX [2][ROWS][XS];
    __shared__ __align__(16) float sH1[2][ROWS][HS];
    __shared__ __align__(16) float sH2[2][ROWS][HS];

    const int tid  = threadIdx.x;
    const int wid  = tid >> 5;
    const int lane = tid & 31;
    const int g    = (wid < 10) ? 0 : 1;       // 0: layer1, 1: layer2
    const int li   = g ? (wid - 10) : wid;     // 0..9 within group
    const int t    = lane / 10;                // k-third 0,1,2 (3 = idle lanes 30,31)
    const int m    = lane % 10;
    const int j    = li * 10 + m;              // unit 0..99
    const int tt   = (t > 2) ? 2 : t;          // clamped third for addresses
    const int r0   = blockIdx.x * ROWS;

    // Weight registers: L1 uses [0..11]=x-part, [12..29]=h-part.
    //                   L2 uses [0..17]=h1-part, [18..35]=h2-part.
    unsigned long long w[36];
    #pragma unroll
    for (int n = 0; n < 36; ++n) w[n] = 0ull;
    float bj;

    if (g == 0) {
        if (t < 3) {
            #pragma unroll
            for (int qi = 0; qi < NXI; ++qi) {
                int q = 3*qi + t;
                if (q < 16) {
                    int k = 4*q;
                    w[2*qi]   = pack2(W1x[(k  )*HH + j], W1x[(k+1)*HH + j]);
                    w[2*qi+1] = pack2(W1x[(k+2)*HH + j], W1x[(k+3)*HH + j]);
                }
            }
            #pragma unroll
            for (int qi = 0; qi < NHI; ++qi) {
                int q = 3*qi + t;
                if (q < 25) {
                    int k = 4*q;
                    w[12+2*qi] = pack2(W1h[(k  )*HH + j], W1h[(k+1)*HH + j]);
                    w[13+2*qi] = pack2(W1h[(k+2)*HH + j], W1h[(k+3)*HH + j]);
                }
            }
        }
        bj = B1[j];
    } else {
        if (t < 3) {
            #pragma unroll
            for (int qi = 0; qi < NHI; ++qi) {
                int q = 3*qi + t;
                if (q < 25) {
                    int k = 4*q;
                    w[2*qi]   = pack2(W2x[(k  )*HH + j], W2x[(k+1)*HH + j]);
                    w[2*qi+1] = pack2(W2x[(k+2)*HH + j], W2x[(k+3)*HH + j]);
                }
            }
            #pragma unroll
            for (int qi = 0; qi < NHI; ++qi) {
                int q = 3*qi + t;
                if (q < 25) {
                    int k = 4*q;
                    w[18+2*qi] = pack2(W2h[(k  )*HH + j], W2h[(k+1)*HH + j]);
                    w[19+2*qi] = pack2(W2h[(k+2)*HH + j], W2h[(k+3)*HH + j]);
                }
            }
        }
        bj = B2[j];
    }

    // Zero ALL shared buffers (states h_{-1}=0, and padding must be finite-0
    // so padded-iteration loads contribute act*0 = 0).
    {
        float* zx = &sX[0][0][0];
        for (int idx = tid; idx < 2*ROWS*XS; idx += NTHR) zx[idx] = 0.f;
        float* z1 = &sH1[0][0][0];
        for (int idx = tid; idx < 2*ROWS*HS; idx += NTHR) z1[idx] = 0.f;
        float* z2 = &sH2[0][0][0];
        for (int idx = tid; idx < 2*ROWS*HS; idx += NTHR) z2[idx] = 0.f;
    }
    __syncthreads();   // pads visible before x0 staging overlaps is fine; keep simple
    // Stage x_0.
    if (tid < 256) {
        int r = tid >> 6, d = tid & 63;
        sX[0][r][d] = X[(size_t)(r0 + r)*TT*DD + d];
    }
    __syncthreads();

    const int lti = li*32 + lane;              // compact index within L1 group

    for (int i = 0; i <= TT; ++i) {
        if (g == 0) {
            // Prefetch x_{i+1} (256 values by first 256 L1 threads).
            float xpf = 0.f;
            const int pr = lti >> 6, pd = lti & 63;
            const bool dopf = (i + 1 < TT) && (lti < 256);
            if (dopf)
                xpf = X[(size_t)(r0 + pr)*TT*DD + (size_t)(i+1)*DD + pd];

            if (i < TT) {
                const int pc = i & 1, pp = pc ^ 1;
                unsigned long long a0=0, a1=0, a2=0, a3=0;
                const float* xb = &sX[pc][0][0] + 4*tt;
                const float* hb = &sH1[pp][0][0] + 4*tt;
                accum4<NXI, 0,  XS>(a0, a1, a2, a3, xb, w);
                accum4<NHI, 12, HS>(a0, a1, a2, a3, hb, w);
                float p0 = hsum2(a0), p1 = hsum2(a1);
                float p2 = hsum2(a2), p3 = hsum2(a3);
                float s0 = combine3(p0), s1 = combine3(p1);
                float s2 = combine3(p2), s3 = combine3(p3);
                if (t == 0) {
                    sH1[pc][0][j] = tanh_f(s0 + bj);
                    sH1[pc][1][j] = tanh_f(s1 + bj);
                    sH1[pc][2][j] = tanh_f(s2 + bj);
                    sH1[pc][3][j] = tanh_f(s3 + bj);
                }
            }
            if (dopf) sX[(i+1) & 1][pr][pd] = xpf;
        } else {
            if (i >= 1) {
                const int s  = i - 1;
                const int pc = s & 1, pp = pc ^ 1;
                unsigned long long a0=0, a1=0, a2=0, a3=0;
                const float* h1b = &sH1[pc][0][0] + 4*tt;
                const float* h2b = &sH2[pp][0][0] + 4*tt;
                accum4<NHI, 0,  HS>(a0, a1, a2, a3, h1b, w);
                accum4<NHI, 18, HS>(a0, a1, a2, a3, h2b, w);
                float p0 = hsum2(a0), p1 = hsum2(a1);
                float p2 = hsum2(a2), p3 = hsum2(a3);
                float s0 = combine3(p0), s1 = combine3(p1);
                float s2 = combine3(p2), s3 = combine3(p3);
                if (t == 0) {
                    sH2[pc][0][j] = tanh_f(s0 + bj);
                    sH2[pc][1][j] = tanh_f(s1 + bj);
                    sH2[pc][2][j] = tanh_f(s2 + bj);
                    sH2[pc][3][j] = tanh_f(s3 + bj);
                }
            }
        }
        __syncthreads();
    }

    // Final states live at parity (TT-1)&1 == 1.
    float* outVec = out;                      // [512]
    float* outH1  = out + BB;                 // [512,100]
    float* outH2  = out + BB + BB*HH;         // [512,100]

    for (int idx = tid; idx < ROWS*HH; idx += NTHR) {
        int r = idx / HH, jj = idx % HH;
        outH1[(size_t)(r0 + r)*HH + jj] = sH1[1][r][jj];
        outH2[(size_t)(r0 + r)*HH + jj] = sH2[1][r][jj];
    }

    // Output head: out[r] = h2_T[r] . Wo + bo  (warp 0 does all 4 rows)
    if (tid < 32) {
        #pragma unroll
        for (int r = 0; r < ROWS; ++r) {
            float v = 0.f;
            #pragma unroll
            for (int mm = 0; mm < 4; ++mm) {
                int jj = mm*32 + tid;
                if (jj < HH) v += sH2[1][r][jj] * Wo[jj];
            }
            #pragma unroll
            for (int off = 16; off; off >>= 1)
                v += __shfl_down_sync(0xffffffffu, v, off);
            if (tid == 0) outVec[r0 + r] = v + Bo[0];
        }
    }
}

extern "C" void kernel_launch(void* const* d_in, const int* in_sizes, int n_in,
                              void* d_out, int out_size) {
    (void)in_sizes; (void)n_in; (void)out_size;
    const float* X   = (const float*)d_in[0];
    const float* W1x = (const float*)d_in[1];
    const float* W1h = (const float*)d_in[2];
    const float* B1  = (const float*)d_in[3];
    const float* W2x = (const float*)d_in[4];
    const float* W2h = (const float*)d_in[5];
    const float* B2  = (const float*)d_in[6];
    const float* Wo  = (const float*)d_in[7];
    const float* Bo  = (const float*)d_in[8];
    drnn_kernel<<<BB/ROWS, NTHR>>>(X, W1x, W1h, B1, W2x, W2h, B2, Wo, Bo,
                                   (float*)d_out);
}